// round 4
// baseline (speedup 1.0000x reference)
#include <cuda_runtime.h>
#include <cuda_bf16.h>

// Problem constants (fixed shapes from reference)
#define BATCH      16
#define TLEN       1024
#define CCH        32
#define TC         (TLEN * CCH)        // 32768
#define KDIM       128
#define S_MAIN     128
#define NB_PATCH   400
#define P_TOP      60
#define P_OUT      (NB_PATCH + P_TOP)  // 460
#define STRETCH    8
#define TASKS_MAIN (S_MAIN * NB_PATCH) // 51200
#define TASKS_TOP  (TLEN * P_TOP)      // 61440
#define TASKS_ALL  (TASKS_MAIN + TASKS_TOP)

// Scratch: transposed x, xT[tc][b] so a gather index pulls 16 contiguous fp32 (64B).
__device__ float g_xT[TC * BATCH];

// --------------------------------------------------------------------------
// Kernel 1: transpose x [B, T*C] -> xT [T*C, B]
// Reads coalesced along tc per batch row; writes 4x float4 per thread.
// --------------------------------------------------------------------------
__global__ void transpose_x_kernel(const float* __restrict__ x) {
    int tc = blockIdx.x * blockDim.x + threadIdx.x;
    if (tc >= TC) return;
    float v[BATCH];
#pragma unroll
    for (int b = 0; b < BATCH; b++) {
        v[b] = x[b * TC + tc];
    }
    float4* dst = reinterpret_cast<float4*>(g_xT + tc * BATCH);
    dst[0] = make_float4(v[0],  v[1],  v[2],  v[3]);
    dst[1] = make_float4(v[4],  v[5],  v[6],  v[7]);
    dst[2] = make_float4(v[8],  v[9],  v[10], v[11]);
    dst[3] = make_float4(v[12], v[13], v[14], v[15]);
}

// --------------------------------------------------------------------------
// Kernel 2: fused main + top patch layers.
// One warp per task. lane = half*16 + b. Each half-warp handles 64 K-entries
// (16x int4/float4 broadcast loads), gathers coalesced 64B xT rows, reduces
// across halves with one shfl_xor.
// --------------------------------------------------------------------------
__global__ __launch_bounds__(256) void patchy_kernel(
    const float* __restrict__ W_main, const float* __restrict__ b_main,
    const float* __restrict__ W_top,  const float* __restrict__ b_top,
    const int*   __restrict__ idx_main, const int* __restrict__ idx_top,
    float* __restrict__ out)
{
    const int warp = (blockIdx.x * blockDim.x + threadIdx.x) >> 5;
    if (warp >= TASKS_ALL) return;
    const int lane = threadIdx.x & 31;
    const int b    = lane & 15;
    const int half = lane >> 4;

    const float* __restrict__ xTb = g_xT + b;

    const int*   ip;
    const float* wp;
    float bias;
    if (warp < TASKS_MAIN) {
        const long base = (long)warp * KDIM + half * 64;
        ip   = idx_main + base;
        wp   = W_main + base;
        bias = b_main[warp];
    } else {
        const int task = warp - TASKS_MAIN;
        const long base = (long)task * KDIM + half * 64;
        ip   = idx_top + base;
        wp   = W_top + base;
        bias = b_top[task];
    }

    // 64 K-entries per half-warp, as 16 int4/float4 chunks.
    float a0 = 0.f, a1 = 0.f, a2 = 0.f, a3 = 0.f;
    const int4*   ip4 = reinterpret_cast<const int4*>(ip);
    const float4* wp4 = reinterpret_cast<const float4*>(wp);
#pragma unroll 4
    for (int i = 0; i < 16; i++) {
        const int4   id = ip4[i];
        const float4 w  = wp4[i];
        a0 = fmaf(xTb[(long)id.x * BATCH], w.x, a0);
        a1 = fmaf(xTb[(long)id.y * BATCH], w.y, a1);
        a2 = fmaf(xTb[(long)id.z * BATCH], w.z, a2);
        a3 = fmaf(xTb[(long)id.w * BATCH], w.w, a3);
    }
    float acc = (a0 + a1) + (a2 + a3);
    // Reduce across the two halves (lane ^ 16 holds the other 64 K-entries).
    acc += __shfl_xor_sync(0xffffffffu, acc, 16);

    float v = acc + bias;
    float y = (v > 0.f) ? v : 0.3f * v;

    if (half == 0) {
        if (warp < TASKS_MAIN) {
            const int s = warp / NB_PATCH;
            const int p = warp - s * NB_PATCH;
            float* o = out + (long)b * TLEN * P_OUT + (long)s * STRETCH * P_OUT + p;
#pragma unroll
            for (int j = 0; j < STRETCH; j++) {
                o[j * P_OUT] = y;   // jnp.repeat along time
            }
        } else {
            const int task = warp - TASKS_MAIN;
            const int t = task / P_TOP;
            const int p = task - t * P_TOP;
            out[(long)b * TLEN * P_OUT + (long)t * P_OUT + NB_PATCH + p] = y;
        }
    }
}

// --------------------------------------------------------------------------
// Launch: transpose, then fused patch kernel (sequential on stream = dep).
// Inputs (metadata order): x, W_main, b_main, W_top, b_top, idx_main, idx_top
// --------------------------------------------------------------------------
extern "C" void kernel_launch(void* const* d_in, const int* in_sizes, int n_in,
                              void* d_out, int out_size) {
    const float* x        = (const float*)d_in[0];
    const float* W_main   = (const float*)d_in[1];
    const float* b_main   = (const float*)d_in[2];
    const float* W_top    = (const float*)d_in[3];
    const float* b_top    = (const float*)d_in[4];
    const int*   idx_main = (const int*)  d_in[5];
    const int*   idx_top  = (const int*)  d_in[6];
    float* out = (float*)d_out;

    transpose_x_kernel<<<(TC + 255) / 256, 256>>>(x);

    const int warps_per_block = 256 / 32;
    const int nblocks = (TASKS_ALL + warps_per_block - 1) / warps_per_block; // 14080
    patchy_kernel<<<nblocks, 256>>>(W_main, b_main, W_top, b_top,
                                    idx_main, idx_top, out);
}

// round 5
// speedup vs baseline: 1.4890x; 1.4890x over previous
#include <cuda_runtime.h>
#include <cuda_bf16.h>

// Problem constants (fixed shapes from reference)
#define BATCH      16
#define TLEN       1024
#define CCH        32
#define TC         (TLEN * CCH)        // 32768
#define KDIM       128
#define S_MAIN     128
#define NB_PATCH   400
#define P_TOP      60
#define P_OUT      (NB_PATCH + P_TOP)  // 460
#define STRETCH    8

#define WPB        16                  // warps (= p columns) per block
#define THREADS    512
#define MAIN_PB    (NB_PATCH / WPB)    // 25
#define TOP_PB     ((P_TOP + WPB - 1) / WPB) // 4 (last block width 12)
#define MAIN_BLOCKS (S_MAIN * MAIN_PB) // 3200
#define TOP_BLOCKS  (TLEN * TOP_PB)    // 4096
#define ALL_BLOCKS  (MAIN_BLOCKS + TOP_BLOCKS)

// Scratch: transposed x, xT[tc][b] so one gather index pulls 16 contiguous fp32 (64B).
__device__ float g_xT[TC * BATCH];

// --------------------------------------------------------------------------
// Kernel 1: transpose x [B, T*C] -> xT [T*C, B]
// --------------------------------------------------------------------------
__global__ void transpose_x_kernel(const float* __restrict__ x) {
    int tc = blockIdx.x * blockDim.x + threadIdx.x;
    if (tc >= TC) return;
    float v[BATCH];
#pragma unroll
    for (int b = 0; b < BATCH; b++) {
        v[b] = x[b * TC + tc];
    }
    float4* dst = reinterpret_cast<float4*>(g_xT + tc * BATCH);
    dst[0] = make_float4(v[0],  v[1],  v[2],  v[3]);
    dst[1] = make_float4(v[4],  v[5],  v[6],  v[7]);
    dst[2] = make_float4(v[8],  v[9],  v[10], v[11]);
    dst[3] = make_float4(v[12], v[13], v[14], v[15]);
}

// --------------------------------------------------------------------------
// Kernel 2: fused main + top patch layers.
// Block = 16 warps = 16 consecutive p of one (s|t) row.
//   Stage A: cooperative coalesced gmem->smem of the block's idx+W slab.
//   Stage B: warp = task. lane = half*16 + b. Half-warp covers 64 K-entries
//            via broadcast LDS.128 of idx/W, gathers coalesced 64B xT rows,
//            shfl_xor(16) cross-half reduction, bias + leaky_relu.
//   Stage C: results staged in padded smem, stored coalesced:
//            warp = batch, lanes = consecutive p (64B STG rows).
// --------------------------------------------------------------------------
__global__ __launch_bounds__(THREADS) void patchy_kernel(
    const float* __restrict__ W_main, const float* __restrict__ b_main,
    const float* __restrict__ W_top,  const float* __restrict__ b_top,
    const int*   __restrict__ idx_main, const int* __restrict__ idx_top,
    float* __restrict__ out)
{
    __shared__ alignas(16) int   s_idx[WPB * KDIM];   // 8 KB
    __shared__ alignas(16) float s_w  [WPB * KDIM];   // 8 KB
    __shared__ float s_res[WPB * 17];                 // padded (gcd(17,32)=1)

    const int tid = threadIdx.x;
    const bool is_main = (blockIdx.x < MAIN_BLOCKS);

    int st, p0, width;
    const int*   gi;
    const float* gw;
    const float* gb;
    if (is_main) {
        st    = blockIdx.x / MAIN_PB;
        p0    = (blockIdx.x - st * MAIN_PB) * WPB;
        width = WPB;
        const long base = ((long)st * NB_PATCH + p0) * KDIM;
        gi = idx_main + base;
        gw = W_main   + base;
        gb = b_main   + st * NB_PATCH + p0;
    } else {
        const int b2 = blockIdx.x - MAIN_BLOCKS;
        st    = b2 / TOP_PB;
        p0    = (b2 - st * TOP_PB) * WPB;
        width = min(WPB, P_TOP - p0);
        const long base = ((long)st * P_TOP + p0) * KDIM;
        gi = idx_top + base;
        gw = W_top   + base;
        gb = b_top   + st * P_TOP + p0;
    }

    // ---- Stage A: coalesced staging of idx + W (width*KDIM ints/floats) ----
    {
        const int n4 = (width * KDIM) >> 2;          // 512 or 384 int4/float4
        const int4*   gi4 = reinterpret_cast<const int4*>(gi);
        const float4* gw4 = reinterpret_cast<const float4*>(gw);
        int4*   si4 = reinterpret_cast<int4*>(s_idx);
        float4* sw4 = reinterpret_cast<float4*>(s_w);
        if (tid < n4) {
            si4[tid] = gi4[tid];
            sw4[tid] = gw4[tid];
        }
    }
    __syncthreads();

    // ---- Stage B: compute ----
    const int w    = tid >> 5;       // warp id == local p
    const int lane = tid & 31;
    const int b    = lane & 15;
    const int half = lane >> 4;

    if (w < width) {
        const float* __restrict__ xTb = g_xT + b;
        const int4*   ip4 = reinterpret_cast<const int4*>(s_idx + w * KDIM + half * 64);
        const float4* wp4 = reinterpret_cast<const float4*>(s_w  + w * KDIM + half * 64);

        float a0 = 0.f, a1 = 0.f, a2 = 0.f, a3 = 0.f;
#pragma unroll 4
        for (int i = 0; i < 16; i++) {
            const int4   id = ip4[i];
            const float4 ww = wp4[i];
            a0 = fmaf(xTb[id.x * BATCH], ww.x, a0);
            a1 = fmaf(xTb[id.y * BATCH], ww.y, a1);
            a2 = fmaf(xTb[id.z * BATCH], ww.z, a2);
            a3 = fmaf(xTb[id.w * BATCH], ww.w, a3);
        }
        float acc = (a0 + a1) + (a2 + a3);
        acc += __shfl_xor_sync(0xffffffffu, acc, 16);  // cross-half reduce

        if (half == 0) {
            const float v = acc + gb[w];
            s_res[w * 17 + b] = (v > 0.f) ? v : 0.3f * v;
        }
    }
    __syncthreads();

    // ---- Stage C: coalesced store. warp = batch, lanes = consecutive p ----
    {
        const int j = lane & 15;          // local p
        if (j < width) {
            const float y = s_res[j * 17 + w];   // stride-17 -> conflict-free
            if (is_main) {
                // half 0 writes time reps 0-3, half 1 writes reps 4-7
                long o = (long)w * TLEN * P_OUT
                       + (long)(st * STRETCH + half * 4) * P_OUT + p0 + j;
#pragma unroll
                for (int r = 0; r < 4; r++) {
                    out[o + (long)r * P_OUT] = y;
                }
            } else if (half == 0) {
                out[(long)w * TLEN * P_OUT + (long)st * P_OUT + NB_PATCH + p0 + j] = y;
            }
        }
    }
}

// --------------------------------------------------------------------------
// Inputs (metadata order): x, W_main, b_main, W_top, b_top, idx_main, idx_top
// --------------------------------------------------------------------------
extern "C" void kernel_launch(void* const* d_in, const int* in_sizes, int n_in,
                              void* d_out, int out_size) {
    const float* x        = (const float*)d_in[0];
    const float* W_main   = (const float*)d_in[1];
    const float* b_main   = (const float*)d_in[2];
    const float* W_top    = (const float*)d_in[3];
    const float* b_top    = (const float*)d_in[4];
    const int*   idx_main = (const int*)  d_in[5];
    const int*   idx_top  = (const int*)  d_in[6];
    float* out = (float*)d_out;

    transpose_x_kernel<<<(TC + 255) / 256, 256>>>(x);

    patchy_kernel<<<ALL_BLOCKS, THREADS>>>(W_main, b_main, W_top, b_top,
                                           idx_main, idx_top, out);
}

// round 6
// speedup vs baseline: 1.5455x; 1.0380x over previous
#include <cuda_runtime.h>
#include <cuda_bf16.h>

// Problem constants (fixed shapes from reference)
#define BATCH      16
#define TLEN       1024
#define CCH        32
#define TC         (TLEN * CCH)        // 32768
#define KDIM       128
#define S_MAIN     128
#define NB_PATCH   400
#define P_TOP      60
#define P_OUT      (NB_PATCH + P_TOP)  // 460
#define STRETCH    8

#define WPB        16                  // warps (= p columns) per block
#define THREADS    512
#define SB         17                  // s_res row stride (conflict-free)
#define MAIN_PB    (NB_PATCH / WPB)    // 25
#define TOP_PB     ((P_TOP + WPB - 1) / WPB) // 4 (last block width 12)
#define MAIN_BLOCKS (S_MAIN * MAIN_PB) // 3200
#define TOP_BLOCKS  (TLEN * TOP_PB)    // 4096
#define ALL_BLOCKS  (MAIN_BLOCKS + TOP_BLOCKS)

// Scratch: transposed x, xT[tc][b] so one gather index pulls 16 contiguous fp32 (64B).
__device__ float g_xT[TC * BATCH];

// --------------------------------------------------------------------------
// Kernel 1: transpose x [B, T*C] -> xT [T*C, B]
// --------------------------------------------------------------------------
__global__ void transpose_x_kernel(const float* __restrict__ x) {
    int tc = blockIdx.x * blockDim.x + threadIdx.x;
    if (tc >= TC) return;
    float v[BATCH];
#pragma unroll
    for (int b = 0; b < BATCH; b++) {
        v[b] = x[b * TC + tc];
    }
    float4* dst = reinterpret_cast<float4*>(g_xT + tc * BATCH);
    dst[0] = make_float4(v[0],  v[1],  v[2],  v[3]);
    dst[1] = make_float4(v[4],  v[5],  v[6],  v[7]);
    dst[2] = make_float4(v[8],  v[9],  v[10], v[11]);
    dst[3] = make_float4(v[12], v[13], v[14], v[15]);
}

// --------------------------------------------------------------------------
// Kernel 2: fused main + top patch layers.
// Block = 16 warps = 16 consecutive p of one (s|t) row. Warp = one task.
// Lane = (q = lane>>2, c = lane&3):
//   - idx/W read directly from gmem, int4/float4 at [m*8+q]: 128B/warp-load
//     (1 wavefront), 8 loads total per task. No staging smem.
//   - quad q gathers row idx[j] with 4 lanes x float4 (batches 4c..4c+3):
//     8 rows per warp-LDG = 8 wavefronts, 16 LDGs = 128 wf (floor).
//   - reduce across quads via shfl_xor(4,8,16); q==0 lanes hold 16 batches.
//   - results staged in padded smem; coalesced store: warp = batch,
//     lanes = consecutive p (64B STG rows), main repeated x8 along time.
// --------------------------------------------------------------------------
__global__ __launch_bounds__(THREADS) void patchy_kernel(
    const float* __restrict__ W_main, const float* __restrict__ b_main,
    const float* __restrict__ W_top,  const float* __restrict__ b_top,
    const int*   __restrict__ idx_main, const int* __restrict__ idx_top,
    float* __restrict__ out)
{
    __shared__ float s_res[WPB * SB];

    const int tid  = threadIdx.x;
    const int w    = tid >> 5;       // warp id == local p
    const int lane = tid & 31;
    const int q    = lane >> 2;      // quad: which sub-index group
    const int c    = lane & 3;       // component: batches 4c..4c+3
    const bool is_main = (blockIdx.x < MAIN_BLOCKS);

    int st, p0, width;
    const int*   gi;
    const float* gw;
    const float* gb;
    if (is_main) {
        st    = blockIdx.x / MAIN_PB;
        p0    = (blockIdx.x - st * MAIN_PB) * WPB;
        width = WPB;
        const long base = ((long)st * NB_PATCH + p0) * KDIM;
        gi = idx_main + base;
        gw = W_main   + base;
        gb = b_main   + st * NB_PATCH + p0;
    } else {
        const int b2 = blockIdx.x - MAIN_BLOCKS;
        st    = b2 / TOP_PB;
        p0    = (b2 - st * TOP_PB) * WPB;
        width = min(WPB, P_TOP - p0);
        const long base = ((long)st * P_TOP + p0) * KDIM;
        gi = idx_top + base;
        gw = W_top   + base;
        gb = b_top   + st * P_TOP + p0;
    }

    if (w < width) {
        const int4*   ip4 = reinterpret_cast<const int4*>(gi + w * KDIM);
        const float4* wp4 = reinterpret_cast<const float4*>(gw + w * KDIM);

        // Preload this lane's idx/W slices: warp touches 128B per load -> 1 wf.
        int4   I[4];
        float4 Wv[4];
#pragma unroll
        for (int m = 0; m < 4; m++) {
            I[m]  = ip4[m * 8 + q];
            Wv[m] = wp4[m * 8 + q];
        }

        const float4* __restrict__ xT4 = reinterpret_cast<const float4*>(g_xT);
        float4 acc = make_float4(0.f, 0.f, 0.f, 0.f);
#pragma unroll
        for (int m = 0; m < 4; m++) {
            const float4 g0 = xT4[I[m].x * 4 + c];
            const float4 g1 = xT4[I[m].y * 4 + c];
            const float4 g2 = xT4[I[m].z * 4 + c];
            const float4 g3 = xT4[I[m].w * 4 + c];
            acc.x = fmaf(g0.x, Wv[m].x, acc.x);
            acc.y = fmaf(g0.y, Wv[m].x, acc.y);
            acc.z = fmaf(g0.z, Wv[m].x, acc.z);
            acc.w = fmaf(g0.w, Wv[m].x, acc.w);
            acc.x = fmaf(g1.x, Wv[m].y, acc.x);
            acc.y = fmaf(g1.y, Wv[m].y, acc.y);
            acc.z = fmaf(g1.z, Wv[m].y, acc.z);
            acc.w = fmaf(g1.w, Wv[m].y, acc.w);
            acc.x = fmaf(g2.x, Wv[m].z, acc.x);
            acc.y = fmaf(g2.y, Wv[m].z, acc.y);
            acc.z = fmaf(g2.z, Wv[m].z, acc.z);
            acc.w = fmaf(g2.w, Wv[m].z, acc.w);
            acc.x = fmaf(g3.x, Wv[m].w, acc.x);
            acc.y = fmaf(g3.y, Wv[m].w, acc.y);
            acc.z = fmaf(g3.z, Wv[m].w, acc.z);
            acc.w = fmaf(g3.w, Wv[m].w, acc.w);
        }

        // Reduce across the 8 quads (lanes c, c+4, ..., c+28).
#pragma unroll
        for (int mask = 4; mask <= 16; mask <<= 1) {
            acc.x += __shfl_xor_sync(0xffffffffu, acc.x, mask);
            acc.y += __shfl_xor_sync(0xffffffffu, acc.y, mask);
            acc.z += __shfl_xor_sync(0xffffffffu, acc.z, mask);
            acc.w += __shfl_xor_sync(0xffffffffu, acc.w, mask);
        }

        if (q == 0) {
            const float bias = gb[w];
            float4 v = make_float4(acc.x + bias, acc.y + bias,
                                   acc.z + bias, acc.w + bias);
            float* r = s_res + w * SB + c * 4;
            r[0] = (v.x > 0.f) ? v.x : 0.3f * v.x;
            r[1] = (v.y > 0.f) ? v.y : 0.3f * v.y;
            r[2] = (v.z > 0.f) ? v.z : 0.3f * v.z;
            r[3] = (v.w > 0.f) ? v.w : 0.3f * v.w;
        }
    }
    __syncthreads();

    // ---- Coalesced store: warp = batch, lanes = consecutive p ----
    {
        const int half = lane >> 4;
        const int j    = lane & 15;          // local p
        if (j < width) {
            const float y = s_res[j * SB + w];   // stride-17 -> conflict-free
            if (is_main) {
                // half 0 writes time reps 0-3, half 1 writes reps 4-7
                long o = (long)w * TLEN * P_OUT
                       + (long)(st * STRETCH + half * 4) * P_OUT + p0 + j;
#pragma unroll
                for (int r = 0; r < 4; r++) {
                    out[o + (long)r * P_OUT] = y;
                }
            } else if (half == 0) {
                out[(long)w * TLEN * P_OUT + (long)st * P_OUT + NB_PATCH + p0 + j] = y;
            }
        }
    }
}

// --------------------------------------------------------------------------
// Inputs (metadata order): x, W_main, b_main, W_top, b_top, idx_main, idx_top
// --------------------------------------------------------------------------
extern "C" void kernel_launch(void* const* d_in, const int* in_sizes, int n_in,
                              void* d_out, int out_size) {
    const float* x        = (const float*)d_in[0];
    const float* W_main   = (const float*)d_in[1];
    const float* b_main   = (const float*)d_in[2];
    const float* W_top    = (const float*)d_in[3];
    const float* b_top    = (const float*)d_in[4];
    const int*   idx_main = (const int*)  d_in[5];
    const int*   idx_top  = (const int*)  d_in[6];
    float* out = (float*)d_out;

    transpose_x_kernel<<<(TC + 255) / 256, 256>>>(x);

    patchy_kernel<<<ALL_BLOCKS, THREADS>>>(W_main, b_main, W_top, b_top,
                                           idx_main, idx_top, out);
}

// round 8
// speedup vs baseline: 1.6150x; 1.0449x over previous
#include <cuda_runtime.h>
#include <cuda_fp16.h>
#include <cuda_bf16.h>
#include <cstdint>

// Problem constants (fixed shapes from reference)
#define BATCH      16
#define TLEN       1024
#define CCH        32
#define TC         (TLEN * CCH)        // 32768
#define KDIM       128
#define S_MAIN     128
#define NB_PATCH   400
#define P_TOP      60
#define P_OUT      (NB_PATCH + P_TOP)  // 460
#define STRETCH    8

#define WPB        16                  // warps (= p columns) per block
#define THREADS    512
#define SB         17                  // s_res row stride (conflict-free)
#define MAIN_PB    (NB_PATCH / WPB)    // 25
#define TOP_PB     ((P_TOP + WPB - 1) / WPB) // 4 (last block width 12)
#define MAIN_BLOCKS (S_MAIN * MAIN_PB) // 3200
#define TOP_BLOCKS  (TLEN * TOP_PB)    // 4096
#define ALL_BLOCKS  (MAIN_BLOCKS + TOP_BLOCKS)

// Scratch: transposed fp16 x, xTh[tc][b]. One gather index pulls 16 halves
// = 32B (one L2 sector) holding all 16 batch values.
__device__ __align__(32) __half g_xTh[TC * BATCH];

// --------------------------------------------------------------------------
// Kernel 1: transpose + fp16-quantize x [B, T*C] -> xTh [T*C, B]
// --------------------------------------------------------------------------
__global__ void transpose_x_kernel(const float* __restrict__ x) {
    int tc = blockIdx.x * blockDim.x + threadIdx.x;
    if (tc >= TC) return;
    __half2 h[8];
#pragma unroll
    for (int b = 0; b < 8; b++) {
        h[b] = __floats2half2_rn(x[(2 * b) * TC + tc], x[(2 * b + 1) * TC + tc]);
    }
    uint4* dst = reinterpret_cast<uint4*>(g_xTh + tc * BATCH);
    unsigned int* hu = reinterpret_cast<unsigned int*>(h);
    dst[0] = make_uint4(hu[0], hu[1], hu[2], hu[3]);
    dst[1] = make_uint4(hu[4], hu[5], hu[6], hu[7]);
}

// --------------------------------------------------------------------------
// Kernel 2: fused main + top patch layers.
// Block = 16 warps = 16 consecutive p of one (s|t) row. Warp = one task.
// Lane = (q = lane>>2, c = lane&3):
//   - idx/W read directly from gmem, int4/float4 at [m*8+q]: 128B/warp-load.
//   - quad q gathers row idx via 4 lanes x 8B (uint2 = 4 halves = batches
//     4c..4c+3): 32B per row, one L2 sector.
//   - reduce across quads via shfl_xor(4,8,16); q==0 lanes hold 16 batches.
//   - results staged in padded smem; coalesced store: warp = batch,
//     lanes = consecutive p (64B STG rows), main repeated x8 along time.
// --------------------------------------------------------------------------
__global__ __launch_bounds__(THREADS) void patchy_kernel(
    const float* __restrict__ W_main, const float* __restrict__ b_main,
    const float* __restrict__ W_top,  const float* __restrict__ b_top,
    const int*   __restrict__ idx_main, const int* __restrict__ idx_top,
    float* __restrict__ out)
{
    __shared__ float s_res[WPB * SB];

    const int tid  = threadIdx.x;
    const int w    = tid >> 5;       // warp id == local p
    const int lane = tid & 31;
    const int q    = lane >> 2;      // quad: which sub-index group
    const int c    = lane & 3;       // component: batches 4c..4c+3
    const bool is_main = (blockIdx.x < MAIN_BLOCKS);

    int st, p0, width;
    const int*   gi;
    const float* gw;
    const float* gb;
    if (is_main) {
        st    = blockIdx.x / MAIN_PB;
        p0    = (blockIdx.x - st * MAIN_PB) * WPB;
        width = WPB;
        const long base = ((long)st * NB_PATCH + p0) * KDIM;
        gi = idx_main + base;
        gw = W_main   + base;
        gb = b_main   + st * NB_PATCH + p0;
    } else {
        const int b2 = blockIdx.x - MAIN_BLOCKS;
        st    = b2 / TOP_PB;
        p0    = (b2 - st * TOP_PB) * WPB;
        width = min(WPB, P_TOP - p0);
        const long base = ((long)st * P_TOP + p0) * KDIM;
        gi = idx_top + base;
        gw = W_top   + base;
        gb = b_top   + st * P_TOP + p0;
    }

    if (w < width) {
        const int4*   ip4 = reinterpret_cast<const int4*>(gi + w * KDIM);
        const float4* wp4 = reinterpret_cast<const float4*>(gw + w * KDIM);

        const uint2* __restrict__ xT2 = reinterpret_cast<const uint2*>(g_xTh);
        float4 acc = make_float4(0.f, 0.f, 0.f, 0.f);

#pragma unroll
        for (int m = 0; m < 4; m++) {
            const int4   I  = ip4[m * 8 + q];   // 128B per warp-load
            const float4 Wv = wp4[m * 8 + q];

            // Gather 4 rows; lane reads its 8B slice (batches 4c..4c+3).
            const uint2 g0 = xT2[I.x * 4 + c];
            const uint2 g1 = xT2[I.y * 4 + c];
            const uint2 g2 = xT2[I.z * 4 + c];
            const uint2 g3 = xT2[I.w * 4 + c];

            const float2 a01 = __half22float2(*reinterpret_cast<const __half2*>(&g0.x));
            const float2 a23 = __half22float2(*reinterpret_cast<const __half2*>(&g0.y));
            const float2 b01 = __half22float2(*reinterpret_cast<const __half2*>(&g1.x));
            const float2 b23 = __half22float2(*reinterpret_cast<const __half2*>(&g1.y));
            const float2 c01 = __half22float2(*reinterpret_cast<const __half2*>(&g2.x));
            const float2 c23 = __half22float2(*reinterpret_cast<const __half2*>(&g2.y));
            const float2 d01 = __half22float2(*reinterpret_cast<const __half2*>(&g3.x));
            const float2 d23 = __half22float2(*reinterpret_cast<const __half2*>(&g3.y));

            acc.x = fmaf(a01.x, Wv.x, acc.x);
            acc.y = fmaf(a01.y, Wv.x, acc.y);
            acc.z = fmaf(a23.x, Wv.x, acc.z);
            acc.w = fmaf(a23.y, Wv.x, acc.w);
            acc.x = fmaf(b01.x, Wv.y, acc.x);
            acc.y = fmaf(b01.y, Wv.y, acc.y);
            acc.z = fmaf(b23.x, Wv.y, acc.z);
            acc.w = fmaf(b23.y, Wv.y, acc.w);
            acc.x = fmaf(c01.x, Wv.z, acc.x);
            acc.y = fmaf(c01.y, Wv.z, acc.y);
            acc.z = fmaf(c23.x, Wv.z, acc.z);
            acc.w = fmaf(c23.y, Wv.z, acc.w);
            acc.x = fmaf(d01.x, Wv.w, acc.x);
            acc.y = fmaf(d01.y, Wv.w, acc.y);
            acc.z = fmaf(d23.x, Wv.w, acc.z);
            acc.w = fmaf(d23.y, Wv.w, acc.w);
        }

        // Reduce across the 8 quads (lanes c, c+4, ..., c+28).
#pragma unroll
        for (int mask = 4; mask <= 16; mask <<= 1) {
            acc.x += __shfl_xor_sync(0xffffffffu, acc.x, mask);
            acc.y += __shfl_xor_sync(0xffffffffu, acc.y, mask);
            acc.z += __shfl_xor_sync(0xffffffffu, acc.z, mask);
            acc.w += __shfl_xor_sync(0xffffffffu, acc.w, mask);
        }

        if (q == 0) {
            const float bias = gb[w];
            float4 v = make_float4(acc.x + bias, acc.y + bias,
                                   acc.z + bias, acc.w + bias);
            float* r = s_res + w * SB + c * 4;
            r[0] = (v.x > 0.f) ? v.x : 0.3f * v.x;
            r[1] = (v.y > 0.f) ? v.y : 0.3f * v.y;
            r[2] = (v.z > 0.f) ? v.z : 0.3f * v.z;
            r[3] = (v.w > 0.f) ? v.w : 0.3f * v.w;
        }
    }
    __syncthreads();

    // ---- Coalesced store: warp = batch, lanes = consecutive p ----
    {
        const int half = lane >> 4;
        const int j    = lane & 15;          // local p
        if (j < width) {
            const float y = s_res[j * SB + w];   // stride-17 -> conflict-free
            if (is_main) {
                // half 0 writes time reps 0-3, half 1 writes reps 4-7
                long o = (long)w * TLEN * P_OUT
                       + (long)(st * STRETCH + half * 4) * P_OUT + p0 + j;
#pragma unroll
                for (int r = 0; r < 4; r++) {
                    out[o + (long)r * P_OUT] = y;
                }
            } else if (half == 0) {
                out[(long)w * TLEN * P_OUT + (long)st * P_OUT + NB_PATCH + p0 + j] = y;
            }
        }
    }
}

// --------------------------------------------------------------------------
// Inputs (metadata order): x, W_main, b_main, W_top, b_top, idx_main, idx_top
// --------------------------------------------------------------------------
extern "C" void kernel_launch(void* const* d_in, const int* in_sizes, int n_in,
                              void* d_out, int out_size) {
    const float* x        = (const float*)d_in[0];
    const float* W_main   = (const float*)d_in[1];
    const float* b_main   = (const float*)d_in[2];
    const float* W_top    = (const float*)d_in[3];
    const float* b_top    = (const float*)d_in[4];
    const int*   idx_main = (const int*)  d_in[5];
    const int*   idx_top  = (const int*)  d_in[6];
    float* out = (float*)d_out;

    transpose_x_kernel<<<(TC + 255) / 256, 256>>>(x);

    patchy_kernel<<<ALL_BLOCKS, THREADS>>>(W_main, b_main, W_top, b_top,
                                           idx_main, idx_top, out);
}

// round 9
// speedup vs baseline: 1.6433x; 1.0175x over previous
#include <cuda_runtime.h>
#include <cuda_fp16.h>
#include <cuda_bf16.h>
#include <cstdint>

// Problem constants (fixed shapes from reference)
#define BATCH      16
#define TLEN       1024
#define CCH        32
#define TC         (TLEN * CCH)        // 32768
#define KDIM       128
#define S_MAIN     128
#define NB_PATCH   400
#define P_TOP      60
#define P_OUT      (NB_PATCH + P_TOP)  // 460
#define STRETCH    8

#define WPB        16                  // warps (= p columns) per block
#define THREADS    512
#define SB         17                  // s_res row stride (conflict-free)
#define MAIN_PB    (NB_PATCH / WPB)    // 25
#define TOP_PB     ((P_TOP + WPB - 1) / WPB) // 4 (last block width 12)
#define MAIN_BLOCKS (S_MAIN * MAIN_PB) // 3200
#define TOP_BLOCKS  (TLEN * TOP_PB)    // 4096
#define ALL_BLOCKS  (MAIN_BLOCKS + TOP_BLOCKS)

// Scratch: transposed fp16 x, xTh[tc][b]. One gather index pulls 16 halves
// = 32B (one L2 sector) holding all 16 batch values.
__device__ __align__(32) __half g_xTh[TC * BATCH];

// --------------------------------------------------------------------------
// Kernel 1: transpose + fp16-quantize x [B, T*C] -> xTh [T*C, B]
// --------------------------------------------------------------------------
__global__ void transpose_x_kernel(const float* __restrict__ x) {
    int tc = blockIdx.x * blockDim.x + threadIdx.x;
    if (tc >= TC) return;
    __half2 h[8];
#pragma unroll
    for (int b = 0; b < 8; b++) {
        h[b] = __floats2half2_rn(x[(2 * b) * TC + tc], x[(2 * b + 1) * TC + tc]);
    }
    uint4* dst = reinterpret_cast<uint4*>(g_xTh + tc * BATCH);
    unsigned int* hu = reinterpret_cast<unsigned int*>(h);
    dst[0] = make_uint4(hu[0], hu[1], hu[2], hu[3]);
    dst[1] = make_uint4(hu[4], hu[5], hu[6], hu[7]);
}

// --------------------------------------------------------------------------
// Kernel 2: fused main + top patch layers.
// Block = 16 warps = 16 consecutive p of one (s|t) row. Warp = one task.
// Lane = (q = lane>>2, c = lane&3).
// MLP-maximized schedule: load all 4 idx int4s, issue ALL 16 gather LDGs
// back-to-back, then W loads, then convert+FMA. ~16 outstanding gathers
// per warp keeps the L1tex queue saturated at ~50% occupancy.
// --------------------------------------------------------------------------
__global__ __launch_bounds__(THREADS) void patchy_kernel(
    const float* __restrict__ W_main, const float* __restrict__ b_main,
    const float* __restrict__ W_top,  const float* __restrict__ b_top,
    const int*   __restrict__ idx_main, const int* __restrict__ idx_top,
    float* __restrict__ out)
{
    __shared__ float s_res[WPB * SB];

    const int tid  = threadIdx.x;
    const int w    = tid >> 5;       // warp id == local p
    const int lane = tid & 31;
    const int q    = lane >> 2;      // quad: which sub-index group
    const int c    = lane & 3;       // component: batches 4c..4c+3
    const bool is_main = (blockIdx.x < MAIN_BLOCKS);

    int st, p0, width;
    const int*   gi;
    const float* gw;
    const float* gb;
    if (is_main) {
        st    = blockIdx.x / MAIN_PB;
        p0    = (blockIdx.x - st * MAIN_PB) * WPB;
        width = WPB;
        const long base = ((long)st * NB_PATCH + p0) * KDIM;
        gi = idx_main + base;
        gw = W_main   + base;
        gb = b_main   + st * NB_PATCH + p0;
    } else {
        const int b2 = blockIdx.x - MAIN_BLOCKS;
        st    = b2 / TOP_PB;
        p0    = (b2 - st * TOP_PB) * WPB;
        width = min(WPB, P_TOP - p0);
        const long base = ((long)st * P_TOP + p0) * KDIM;
        gi = idx_top + base;
        gw = W_top   + base;
        gb = b_top   + st * P_TOP + p0;
    }

    if (w < width) {
        const int4*   ip4 = reinterpret_cast<const int4*>(gi + w * KDIM);
        const float4* wp4 = reinterpret_cast<const float4*>(gw + w * KDIM);
        const uint2* __restrict__ xT2 = reinterpret_cast<const uint2*>(g_xTh);

        // ---- Phase 1: all idx loads (4x LDG.128, each 1 wavefront) ----
        int4 I[4];
#pragma unroll
        for (int m = 0; m < 4; m++) I[m] = ip4[m * 8 + q];

        // ---- Phase 2: all 16 gathers issued back-to-back (max MLP) ----
        uint2 G[16];
#pragma unroll
        for (int m = 0; m < 4; m++) {
            G[m * 4 + 0] = xT2[I[m].x * 4 + c];
            G[m * 4 + 1] = xT2[I[m].y * 4 + c];
            G[m * 4 + 2] = xT2[I[m].z * 4 + c];
            G[m * 4 + 3] = xT2[I[m].w * 4 + c];
        }

        // ---- Phase 3: W loads (independent of gathers) ----
        float4 Wv[4];
#pragma unroll
        for (int m = 0; m < 4; m++) Wv[m] = wp4[m * 8 + q];

        // ---- Phase 4: convert + FMA ----
        float4 acc = make_float4(0.f, 0.f, 0.f, 0.f);
#pragma unroll
        for (int m = 0; m < 4; m++) {
            const float wv[4] = { Wv[m].x, Wv[m].y, Wv[m].z, Wv[m].w };
#pragma unroll
            for (int j = 0; j < 4; j++) {
                const uint2 g = G[m * 4 + j];
                const float2 lo = __half22float2(*reinterpret_cast<const __half2*>(&g.x));
                const float2 hi = __half22float2(*reinterpret_cast<const __half2*>(&g.y));
                acc.x = fmaf(lo.x, wv[j], acc.x);
                acc.y = fmaf(lo.y, wv[j], acc.y);
                acc.z = fmaf(hi.x, wv[j], acc.z);
                acc.w = fmaf(hi.y, wv[j], acc.w);
            }
        }

        // Reduce across the 8 quads (lanes c, c+4, ..., c+28).
#pragma unroll
        for (int mask = 4; mask <= 16; mask <<= 1) {
            acc.x += __shfl_xor_sync(0xffffffffu, acc.x, mask);
            acc.y += __shfl_xor_sync(0xffffffffu, acc.y, mask);
            acc.z += __shfl_xor_sync(0xffffffffu, acc.z, mask);
            acc.w += __shfl_xor_sync(0xffffffffu, acc.w, mask);
        }

        if (q == 0) {
            const float bias = gb[w];
            float4 v = make_float4(acc.x + bias, acc.y + bias,
                                   acc.z + bias, acc.w + bias);
            float* r = s_res + w * SB + c * 4;
            r[0] = (v.x > 0.f) ? v.x : 0.3f * v.x;
            r[1] = (v.y > 0.f) ? v.y : 0.3f * v.y;
            r[2] = (v.z > 0.f) ? v.z : 0.3f * v.z;
            r[3] = (v.w > 0.f) ? v.w : 0.3f * v.w;
        }
    }
    __syncthreads();

    // ---- Coalesced store: warp = batch, lanes = consecutive p ----
    {
        const int half = lane >> 4;
        const int j    = lane & 15;          // local p
        if (j < width) {
            const float y = s_res[j * SB + w];   // stride-17 -> conflict-free
            if (is_main) {
                // half 0 writes time reps 0-3, half 1 writes reps 4-7
                long o = (long)w * TLEN * P_OUT
                       + (long)(st * STRETCH + half * 4) * P_OUT + p0 + j;
#pragma unroll
                for (int r = 0; r < 4; r++) {
                    out[o + (long)r * P_OUT] = y;
                }
            } else if (half == 0) {
                out[(long)w * TLEN * P_OUT + (long)st * P_OUT + NB_PATCH + p0 + j] = y;
            }
        }
    }
}

// --------------------------------------------------------------------------
// Inputs (metadata order): x, W_main, b_main, W_top, b_top, idx_main, idx_top
// --------------------------------------------------------------------------
extern "C" void kernel_launch(void* const* d_in, const int* in_sizes, int n_in,
                              void* d_out, int out_size) {
    const float* x        = (const float*)d_in[0];
    const float* W_main   = (const float*)d_in[1];
    const float* b_main   = (const float*)d_in[2];
    const float* W_top    = (const float*)d_in[3];
    const float* b_top    = (const float*)d_in[4];
    const int*   idx_main = (const int*)  d_in[5];
    const int*   idx_top  = (const int*)  d_in[6];
    float* out = (float*)d_out;

    transpose_x_kernel<<<(TC + 255) / 256, 256>>>(x);

    patchy_kernel<<<ALL_BLOCKS, THREADS>>>(W_main, b_main, W_top, b_top,
                                           idx_main, idx_top, out);
}